// round 6
// baseline (speedup 1.0000x reference)
#include <cuda_runtime.h>
#include <cuda_bf16.h>
#include <cstdint>

// YOLO loss: pred [16384,7,7,30] f32, target [16384,7,7,30] f32 -> scalar f32.
// Pure HBM-bound reduction (192.6 MB in, 4 B out).
//
// R6: TMA double-buffer as R5, but 7 blocks/SM (64-thread blocks, 64-cell
// chunks, 30720B smem each) -> 7 independent TMA streams per SM at finer
// (7680B) grain, plus L2 evict_first policy on the bulk copies (zero reuse).

#define S 7
#define CELLS_PER_IMG 49
#define NCH 30
#define BATCH 16384
#define TOTAL_CELLS (BATCH * CELLS_PER_IMG)    // 802816
#define BLOCK_THREADS 64
#define CHUNK_CELLS 64
#define NCHUNKS (TOTAL_CELLS / CHUNK_CELLS)    // 12544
#define GRID (148 * 7)                         // 1036
#define CHUNK_FLOATS (CHUNK_CELLS * NCH)       // 1920
#define CHUNK_BYTES (CHUNK_FLOATS * 4)         // 7680
#define STAGE_FLOATS (2 * CHUNK_FLOATS)        // pred + tgt
#define STAGE_BYTES (2 * CHUNK_BYTES)          // 15360
#define SMEM_BYTES (2 * STAGE_BYTES)           // 30720
#define STEP (1.0f / 7.0f)
#define LAMBDA_COORD 5.0f
#define LAMBDA_NOOBJ 0.5f

__device__ float g_partials[GRID];
__device__ unsigned int g_count;   // zero-init; reset by last block each launch

struct Box { float x1, y1, x2, y2; };

__device__ __forceinline__ Box convert_box(float x, float y, float w, float h,
                                           float gi, float gj) {
    float cx = (x + gi) * STEP;
    float cy = (y + gj) * STEP;
    Box b;
    b.x1 = fmaxf(cx - 0.5f * w, 0.0f);
    b.y1 = fmaxf(cy - 0.5f * h, 0.0f);
    b.x2 = fminf(cx + 0.5f * w, 1.0f);
    b.y2 = fminf(cy + 0.5f * h, 1.0f);
    return b;
}

__device__ __forceinline__ float iou(const Box& t, const Box& p) {
    // Faithful to reference: inter not clamped; zero if inter <= 0.
    float minx = fmaxf(t.x1, p.x1);
    float miny = fmaxf(t.y1, p.y1);
    float maxx = fminf(t.x2, p.x2);
    float maxy = fminf(t.y2, p.y2);
    float inter = (maxy - miny) * (maxx - minx);
    float uni = (p.x2 - p.x1) * (p.y2 - p.y1)
              + (t.y2 - t.y1) * (t.x2 - t.x1) - inter;
    return (inter > 0.0f) ? inter / (uni + 1e-05f) : 0.0f;
}

__device__ __forceinline__ uint32_t smem_u32(const void* p) {
    return (uint32_t)__cvta_generic_to_shared(p);
}

__device__ __forceinline__ void mbar_init(uint32_t mbar, uint32_t count) {
    asm volatile("mbarrier.init.shared.b64 [%0], %1;" :: "r"(mbar), "r"(count)
                 : "memory");
}

__device__ __forceinline__ void mbar_expect_tx(uint32_t mbar, uint32_t bytes) {
    asm volatile("mbarrier.arrive.expect_tx.shared.b64 _, [%0], %1;"
                 :: "r"(mbar), "r"(bytes) : "memory");
}

__device__ __forceinline__ uint64_t evict_first_policy() {
    uint64_t pol;
    asm("createpolicy.fractional.L2::evict_first.b64 %0, 1.0;" : "=l"(pol));
    return pol;
}

__device__ __forceinline__ void bulk_g2s(uint32_t sdst, const void* gsrc,
                                         uint32_t bytes, uint32_t mbar,
                                         uint64_t pol) {
    asm volatile(
        "cp.async.bulk.shared::cta.global.mbarrier::complete_tx::bytes"
        ".L2::cache_hint [%0], [%1], %2, [%3], %4;"
        :: "r"(sdst), "l"(gsrc), "r"(bytes), "r"(mbar), "l"(pol) : "memory");
}

__device__ __forceinline__ void mbar_wait(uint32_t mbar, uint32_t parity) {
    asm volatile(
        "{\n\t"
        ".reg .pred P;\n\t"
        "WAIT_%=: \n\t"
        "mbarrier.try_wait.parity.acquire.cta.shared::cta.b64 P, [%0], %1, 0x989680;\n\t"
        "@P bra.uni DONE_%=;\n\t"
        "bra.uni WAIT_%=;\n\t"
        "DONE_%=: \n\t"
        "}"
        :: "r"(mbar), "r"(parity) : "memory");
}

__global__ void __launch_bounds__(BLOCK_THREADS)
yolo_loss_tma7(const float* __restrict__ pred, const float* __restrict__ tgt,
               float* __restrict__ out) {
    extern __shared__ __align__(128) float sbuf[];   // 2 stages, 30720 B
    __shared__ __align__(8) uint64_t mbar_s[2];
    __shared__ float wsum[BLOCK_THREADS / 32];
    __shared__ int s_islast;

    const int tid = threadIdx.x;
    const uint32_t mbar0 = smem_u32(&mbar_s[0]);
    const uint32_t mbar1 = smem_u32(&mbar_s[1]);
    const uint64_t pol = evict_first_policy();

    if (tid == 0) {
        mbar_init(mbar0, 1);
        mbar_init(mbar1, 1);
    }
    __syncthreads();

    // Prologue: issue chunks for iterations 0 and 1.
    if (tid == 0) {
        int c0 = blockIdx.x;
        if (c0 < NCHUNKS) {
            mbar_expect_tx(mbar0, STAGE_BYTES);
            bulk_g2s(smem_u32(sbuf), pred + (size_t)c0 * CHUNK_FLOATS,
                     CHUNK_BYTES, mbar0, pol);
            bulk_g2s(smem_u32(sbuf + CHUNK_FLOATS),
                     tgt + (size_t)c0 * CHUNK_FLOATS, CHUNK_BYTES, mbar0, pol);
        }
        int c1 = c0 + GRID;
        if (c1 < NCHUNKS) {
            mbar_expect_tx(mbar1, STAGE_BYTES);
            bulk_g2s(smem_u32(sbuf + STAGE_FLOATS),
                     pred + (size_t)c1 * CHUNK_FLOATS, CHUNK_BYTES, mbar1, pol);
            bulk_g2s(smem_u32(sbuf + STAGE_FLOATS + CHUNK_FLOATS),
                     tgt + (size_t)c1 * CHUNK_FLOATS, CHUNK_BYTES, mbar1, pol);
        }
    }

    float acc = 0.0f;
    int ph0 = 0, ph1 = 0;
    int it = 0;
    for (int c = blockIdx.x; c < NCHUNKS; c += GRID, it++) {
        const int b = it & 1;
        if (b == 0) { mbar_wait(mbar0, ph0); ph0 ^= 1; }
        else        { mbar_wait(mbar1, ph1); ph1 ^= 1; }

        const float* P = sbuf + b * STAGE_FLOATS + tid * NCH;
        const float* T = sbuf + b * STAGE_FLOATS + CHUNK_FLOATS + tid * NCH;

        const int cell = c * CHUNK_CELLS + tid;
        const int r = cell % CELLS_PER_IMG;
        const float gi = (float)(r / S);
        const float gj = (float)(r % S);

        const float t0 = T[0], t1 = T[1], t2 = T[2], t3 = T[3], tconf = T[4];
        Box tb = convert_box(t0, t1, t2, t3, gi, gj);
        Box pb1 = convert_box(P[0], P[1], P[2], P[3], gi, gj);
        Box pb2 = convert_box(P[5], P[6], P[7], P[8], gi, gj);
        float iou1 = iou(tb, pb1);
        float iou2 = iou(tb, pb2);

        bool sel2 = (iou1 <= iou2);
        float conf_t = sel2 ? iou2 : iou1;
        float px = sel2 ? P[5] : P[0];
        float py = sel2 ? P[6] : P[1];
        float pw = sel2 ? P[7] : P[2];
        float ph = sel2 ? P[8] : P[3];
        float pconf = sel2 ? P[9] : P[4];

        float obj = (tconf > 0.0f) ? 1.0f : 0.0f;
        float noobj = (tconf == 0.0f) ? 1.0f : 0.0f;

        float dconf = pconf - conf_t;
        float dx = px - t0, dy = py - t1, dw = pw - t2, dh = ph - t3;
        float coord = dx * dx + dy * dy + dw * dw + dh * dh;

        float cls = 0.0f;
#pragma unroll
        for (int k = 10; k < NCH; k++) {
            float d = P[k] - T[k];
            cls = fmaf(d, d, cls);
        }

        float d4 = P[4] - T[4];
        float d9 = P[9] - T[9];
        float noobj_term = d4 * d4 + d9 * d9;

        acc += obj * (dconf * dconf + LAMBDA_COORD * coord + cls)
             + LAMBDA_NOOBJ * noobj * noobj_term;

        __syncthreads();   // all threads done reading buffer b

        const int nc = c + 2 * GRID;
        if (tid == 0 && nc < NCHUNKS) {
            const uint32_t mb = b ? mbar1 : mbar0;
            mbar_expect_tx(mb, STAGE_BYTES);
            bulk_g2s(smem_u32(sbuf + b * STAGE_FLOATS),
                     pred + (size_t)nc * CHUNK_FLOATS, CHUNK_BYTES, mb, pol);
            bulk_g2s(smem_u32(sbuf + b * STAGE_FLOATS + CHUNK_FLOATS),
                     tgt + (size_t)nc * CHUNK_FLOATS, CHUNK_BYTES, mb, pol);
        }
    }

    // Block reduction (2 warps).
#pragma unroll
    for (int off = 16; off > 0; off >>= 1)
        acc += __shfl_down_sync(0xFFFFFFFFu, acc, off);
    if ((tid & 31) == 0) wsum[tid >> 5] = acc;
    __syncthreads();

    if (tid == 0) {
        float s = wsum[0] + wsum[1];
        g_partials[blockIdx.x] = s;
        __threadfence();
        unsigned int old = atomicAdd(&g_count, 1u);
        s_islast = (old == GRID - 1u) ? 1 : 0;
    }
    __syncthreads();

    if (s_islast) {
        // Fixed-order final reduce by the last block (deterministic).
        volatile float* vp = g_partials;
        float s = 0.0f;
        for (int i = tid; i < GRID; i += BLOCK_THREADS) s += vp[i];
#pragma unroll
        for (int off = 16; off > 0; off >>= 1)
            s += __shfl_down_sync(0xFFFFFFFFu, s, off);
        if ((tid & 31) == 0) wsum[tid >> 5] = s;
        __syncthreads();
        if (tid == 0) {
            out[0] = (wsum[0] + wsum[1]) * (1.0f / (float)BATCH);
            __threadfence();
            g_count = 0u;   // reset for next graph replay
        }
    }
}

extern "C" void kernel_launch(void* const* d_in, const int* in_sizes, int n_in,
                              void* d_out, int out_size) {
    const float* pred = (const float*)d_in[0];
    const float* tgt  = (const float*)d_in[1];
    float* out = (float*)d_out;

    cudaFuncSetAttribute(yolo_loss_tma7,
                         cudaFuncAttributeMaxDynamicSharedMemorySize,
                         SMEM_BYTES);
    yolo_loss_tma7<<<GRID, BLOCK_THREADS, SMEM_BYTES>>>(pred, tgt, out);
}

// round 7
// speedup vs baseline: 1.1150x; 1.1150x over previous
#include <cuda_runtime.h>
#include <cuda_bf16.h>
#include <cstdint>

// YOLO loss: pred [16384,7,7,30] f32, target [16384,7,7,30] f32 -> scalar f32.
// Pure HBM-bound reduction (192.6 MB in, 4 B out).
//
// R7: R5 (TMA bulk, 15360B chunks, 128-thread blocks, fused last-block tail)
// but with a 3-stage pipeline: 92160B smem/block, 2 blocks/SM (GRID=296).
// During each compute window 2 chunks/block are in flight, hiding the
// per-iteration overhead (mbar wait + syncthreads + issue) from DRAM.

#define S 7
#define CELLS_PER_IMG 49
#define NCH 30
#define BATCH 16384
#define TOTAL_CELLS (BATCH * CELLS_PER_IMG)    // 802816
#define BLOCK_CELLS 128
#define NCHUNKS (TOTAL_CELLS / BLOCK_CELLS)    // 6272
#define GRID 296                               // 148 SMs * 2
#define NSTAGES 3
#define CHUNK_FLOATS (BLOCK_CELLS * NCH)       // 3840
#define CHUNK_BYTES (CHUNK_FLOATS * 4)         // 15360
#define STAGE_FLOATS (2 * CHUNK_FLOATS)        // pred + tgt
#define STAGE_BYTES (2 * CHUNK_BYTES)          // 30720
#define SMEM_BYTES (NSTAGES * STAGE_BYTES)     // 92160
#define STEP (1.0f / 7.0f)
#define LAMBDA_COORD 5.0f
#define LAMBDA_NOOBJ 0.5f

__device__ float g_partials[GRID];
__device__ unsigned int g_count;   // zero-init; reset by last block each launch

struct Box { float x1, y1, x2, y2; };

__device__ __forceinline__ Box convert_box(float x, float y, float w, float h,
                                           float gi, float gj) {
    float cx = (x + gi) * STEP;
    float cy = (y + gj) * STEP;
    Box b;
    b.x1 = fmaxf(cx - 0.5f * w, 0.0f);
    b.y1 = fmaxf(cy - 0.5f * h, 0.0f);
    b.x2 = fminf(cx + 0.5f * w, 1.0f);
    b.y2 = fminf(cy + 0.5f * h, 1.0f);
    return b;
}

__device__ __forceinline__ float iou(const Box& t, const Box& p) {
    // Faithful to reference: inter not clamped; zero if inter <= 0.
    float minx = fmaxf(t.x1, p.x1);
    float miny = fmaxf(t.y1, p.y1);
    float maxx = fminf(t.x2, p.x2);
    float maxy = fminf(t.y2, p.y2);
    float inter = (maxy - miny) * (maxx - minx);
    float uni = (p.x2 - p.x1) * (p.y2 - p.y1)
              + (t.y2 - t.y1) * (t.x2 - t.x1) - inter;
    return (inter > 0.0f) ? inter / (uni + 1e-05f) : 0.0f;
}

__device__ __forceinline__ uint32_t smem_u32(const void* p) {
    return (uint32_t)__cvta_generic_to_shared(p);
}

__device__ __forceinline__ void mbar_init(uint32_t mbar, uint32_t count) {
    asm volatile("mbarrier.init.shared.b64 [%0], %1;" :: "r"(mbar), "r"(count)
                 : "memory");
}

__device__ __forceinline__ void mbar_expect_tx(uint32_t mbar, uint32_t bytes) {
    asm volatile("mbarrier.arrive.expect_tx.shared.b64 _, [%0], %1;"
                 :: "r"(mbar), "r"(bytes) : "memory");
}

__device__ __forceinline__ void bulk_g2s(uint32_t sdst, const void* gsrc,
                                         uint32_t bytes, uint32_t mbar) {
    asm volatile(
        "cp.async.bulk.shared::cta.global.mbarrier::complete_tx::bytes "
        "[%0], [%1], %2, [%3];"
        :: "r"(sdst), "l"(gsrc), "r"(bytes), "r"(mbar) : "memory");
}

__device__ __forceinline__ void mbar_wait(uint32_t mbar, uint32_t parity) {
    asm volatile(
        "{\n\t"
        ".reg .pred P;\n\t"
        "WAIT_%=: \n\t"
        "mbarrier.try_wait.parity.acquire.cta.shared::cta.b64 P, [%0], %1, 0x989680;\n\t"
        "@P bra.uni DONE_%=;\n\t"
        "bra.uni WAIT_%=;\n\t"
        "DONE_%=: \n\t"
        "}"
        :: "r"(mbar), "r"(parity) : "memory");
}

__device__ __forceinline__ void issue_stage(int chunk, int stage, float* sbuf,
                                            const float* __restrict__ pred,
                                            const float* __restrict__ tgt,
                                            uint32_t mbar) {
    mbar_expect_tx(mbar, STAGE_BYTES);
    float* dst = sbuf + stage * STAGE_FLOATS;
    bulk_g2s(smem_u32(dst), pred + (size_t)chunk * CHUNK_FLOATS,
             CHUNK_BYTES, mbar);
    bulk_g2s(smem_u32(dst + CHUNK_FLOATS), tgt + (size_t)chunk * CHUNK_FLOATS,
             CHUNK_BYTES, mbar);
}

__global__ void __launch_bounds__(BLOCK_CELLS)
yolo_loss_tma3(const float* __restrict__ pred, const float* __restrict__ tgt,
               float* __restrict__ out) {
    extern __shared__ __align__(128) float sbuf[];   // 3 stages, 92160 B
    __shared__ __align__(8) uint64_t mbar_s[NSTAGES];
    __shared__ float wsum[BLOCK_CELLS / 32];
    __shared__ int s_islast;

    const int tid = threadIdx.x;
    uint32_t mbar[NSTAGES];
#pragma unroll
    for (int s = 0; s < NSTAGES; s++) mbar[s] = smem_u32(&mbar_s[s]);

    if (tid == 0) {
#pragma unroll
        for (int s = 0; s < NSTAGES; s++) mbar_init(mbar[s], 1);
    }
    __syncthreads();

    // Prologue: fill all 3 stages.
    if (tid == 0) {
#pragma unroll
        for (int s = 0; s < NSTAGES; s++) {
            int c = blockIdx.x + s * GRID;
            if (c < NCHUNKS) issue_stage(c, s, sbuf, pred, tgt, mbar[s]);
        }
    }

    float acc = 0.0f;
    int phase[NSTAGES] = {0, 0, 0};
    int b = 0;
    for (int c = blockIdx.x; c < NCHUNKS; c += GRID) {
        mbar_wait(mbar[b], phase[b]);
        phase[b] ^= 1;

        const float* P = sbuf + b * STAGE_FLOATS + tid * NCH;
        const float* T = sbuf + b * STAGE_FLOATS + CHUNK_FLOATS + tid * NCH;

        const int cell = c * BLOCK_CELLS + tid;
        const int r = cell % CELLS_PER_IMG;
        const float gi = (float)(r / S);
        const float gj = (float)(r % S);

        const float t0 = T[0], t1 = T[1], t2 = T[2], t3 = T[3], tconf = T[4];
        Box tb = convert_box(t0, t1, t2, t3, gi, gj);
        Box pb1 = convert_box(P[0], P[1], P[2], P[3], gi, gj);
        Box pb2 = convert_box(P[5], P[6], P[7], P[8], gi, gj);
        float iou1 = iou(tb, pb1);
        float iou2 = iou(tb, pb2);

        bool sel2 = (iou1 <= iou2);
        float conf_t = sel2 ? iou2 : iou1;
        float px = sel2 ? P[5] : P[0];
        float py = sel2 ? P[6] : P[1];
        float pw = sel2 ? P[7] : P[2];
        float ph = sel2 ? P[8] : P[3];
        float pconf = sel2 ? P[9] : P[4];

        float obj = (tconf > 0.0f) ? 1.0f : 0.0f;
        float noobj = (tconf == 0.0f) ? 1.0f : 0.0f;

        float dconf = pconf - conf_t;
        float dx = px - t0, dy = py - t1, dw = pw - t2, dh = ph - t3;
        float coord = dx * dx + dy * dy + dw * dw + dh * dh;

        float cls = 0.0f;
#pragma unroll
        for (int k = 10; k < NCH; k++) {
            float d = P[k] - T[k];
            cls = fmaf(d, d, cls);
        }

        float d4 = P[4] - T[4];
        float d9 = P[9] - T[9];
        float noobj_term = d4 * d4 + d9 * d9;

        acc += obj * (dconf * dconf + LAMBDA_COORD * coord + cls)
             + LAMBDA_NOOBJ * noobj * noobj_term;

        __syncthreads();   // all threads done reading stage b

        const int nc = c + NSTAGES * GRID;
        if (tid == 0 && nc < NCHUNKS)
            issue_stage(nc, b, sbuf, pred, tgt, mbar[b]);

        b = (b + 1 == NSTAGES) ? 0 : b + 1;
    }

    // Block reduction.
#pragma unroll
    for (int off = 16; off > 0; off >>= 1)
        acc += __shfl_down_sync(0xFFFFFFFFu, acc, off);
    if ((tid & 31) == 0) wsum[tid >> 5] = acc;
    __syncthreads();

    if (tid == 0) {
        float s = wsum[0];
#pragma unroll
        for (int w = 1; w < BLOCK_CELLS / 32; w++) s += wsum[w];
        g_partials[blockIdx.x] = s;
        __threadfence();
        unsigned int old = atomicAdd(&g_count, 1u);
        s_islast = (old == GRID - 1u) ? 1 : 0;
    }
    __syncthreads();

    if (s_islast) {
        // Fixed-order final reduce by the last block (deterministic).
        volatile float* vp = g_partials;
        float s = 0.0f;
        for (int i = tid; i < GRID; i += BLOCK_CELLS) s += vp[i];
#pragma unroll
        for (int off = 16; off > 0; off >>= 1)
            s += __shfl_down_sync(0xFFFFFFFFu, s, off);
        if ((tid & 31) == 0) wsum[tid >> 5] = s;
        __syncthreads();
        if (tid == 0) {
            float tot = wsum[0];
#pragma unroll
            for (int w = 1; w < BLOCK_CELLS / 32; w++) tot += wsum[w];
            out[0] = tot * (1.0f / (float)BATCH);
            __threadfence();
            g_count = 0u;   // reset for next graph replay
        }
    }
}

extern "C" void kernel_launch(void* const* d_in, const int* in_sizes, int n_in,
                              void* d_out, int out_size) {
    const float* pred = (const float*)d_in[0];
    const float* tgt  = (const float*)d_in[1];
    float* out = (float*)d_out;

    cudaFuncSetAttribute(yolo_loss_tma3,
                         cudaFuncAttributeMaxDynamicSharedMemorySize,
                         SMEM_BYTES);
    yolo_loss_tma3<<<GRID, BLOCK_CELLS, SMEM_BYTES>>>(pred, tgt, out);
}